// round 1
// baseline (speedup 1.0000x reference)
#include <cuda_runtime.h>

#define Hh 128
#define Ww 128
#define NB 32
#define CCH 16
#define NITER 30

#define TW 32
#define TH 16
#define IW 34
#define IH 18
#define IWP 35   // padded smem row (odd -> conflict-free half-warp rows)

// persistent state (no allocation allowed)
__device__ float g_cellA[NB*CCH*Hh*Ww];
__device__ float g_cur[NB*CCH*Hh*Ww];
__device__ unsigned char g_pre[NB*Hh*Ww];

__device__ __forceinline__ unsigned long long pk2(float a, float b){
    unsigned long long r; asm("mov.b64 %0, {%1,%2};" : "=l"(r) : "f"(a), "f"(b)); return r;
}
__device__ __forceinline__ void fma2(unsigned long long &d, unsigned long long a, unsigned long long b){
    asm("fma.rn.f32x2 %0, %1, %2, %0;" : "+l"(d) : "l"(a), "l"(b));
}
__device__ __forceinline__ float lo2(unsigned long long v){ return __uint_as_float((unsigned)v); }
__device__ __forceinline__ float hi2(unsigned long long v){ return __uint_as_float((unsigned)(v>>32)); }

// Build initial 16-channel cell state from 10-channel input
__global__ void init_kernel(const float* __restrict__ inp){
    int p = blockIdx.x*blockDim.x + threadIdx.x;
    const int total = NB*CCH*Hh*Ww;
    if (p >= total) return;
    int hw = p % (Hh*Ww);
    int c  = (p / (Hh*Ww)) % CCH;
    int n  = p / (CCH*Hh*Ww);
    float v;
    if (c == 0)       v = 1.0f - inp[(n*10 + 0)*Hh*Ww + hw];
    else if (c <= 10) v = inp[(n*10 + (c-1))*Hh*Ww + hw];
    else              v = 0.0f;
    g_cellA[p] = v;
}

// Kernel 1: perception + W1(relu) + W2 + residual -> cur; also pre-mask byte.
__global__ void __launch_bounds__(128, 3)
step_kernel(const float* __restrict__ w1, const float* __restrict__ w2)
{
    extern __shared__ float smem[];
    float* sc = smem;                                                    // 16*18*35 floats
    unsigned long long* sw1 = (unsigned long long*)(smem + CCH*IH*IWP);  // 2304 splatted pairs
    float2* sw2p = (float2*)(smem + CCH*IH*IWP + 2*48*48);               // [24][16] float2

    const int tid = threadIdx.x;
    const int bx = blockIdx.x, by = blockIdx.y, n = blockIdx.z;
    const int gx0 = bx*TW, gy0 = by*TH;

    // splat w1 into f32x2 pairs; pack w2 column-pairs
    for (int i = tid; i < 48*48; i += 128) {
        float w = w1[i];
        sw1[i] = pk2(w, w);
    }
    for (int i = tid; i < 16*24; i += 128) {
        int j = i & 15, op = i >> 4;
        sw2p[op*16 + j] = make_float2(w2[j*48 + 2*op], w2[j*48 + 2*op + 1]);
    }
    // load cell tile with 1-pixel halo (zero padded)
    for (int i = tid; i < CCH*IH*IW; i += 128) {
        int sx = i % IW;
        int sy = (i / IW) % IH;
        int c  = i / (IW*IH);
        int gx = gx0 + sx - 1, gy = gy0 + sy - 1;
        float v = 0.0f;
        if (gx >= 0 && gx < Ww && gy >= 0 && gy < Hh)
            v = g_cellA[((n*CCH + c)*Hh + gy)*Ww + gx];
        sc[(c*IH + sy)*IWP + sx] = v;
    }
    __syncthreads();

    for (int pass = 0; pass < 2; pass++) {
        const int pp = tid + pass*128;     // 0..255 pixel-pairs
        const int r  = pp >> 4;            // tile row 0..15
        const int ix = pp & 15;            // pair index 0..15 (x0 = 2*ix)
        const int sy = r + 1;
        const int sx = 2*ix + 1;

        // ---- perception: 48 packed channels (cell, sobel-x, sobel-y) ----
        unsigned long long perc[48];
        float premax_lo = -1e30f, premax_hi = -1e30f;
        #pragma unroll
        for (int c = 0; c < CCH; c++) {
            const float* b0 = sc + (c*IH + (sy-1))*IWP + (sx-1);
            const float* b1 = b0 + IWP;
            const float* b2 = b1 + IWP;
            float a0=b0[0],a1=b0[1],a2=b0[2],a3=b0[3];
            float m0=b1[0],m1=b1[1],m2=b1[2],m3=b1[3];
            float q0=b2[0],q1=b2[1],q2=b2[2],q3=b2[3];
            float gxl = ((a2 - a0) + 2.f*(m2 - m0) + (q2 - q0)) * 0.125f;
            float gxh = ((a3 - a1) + 2.f*(m3 - m1) + (q3 - q1)) * 0.125f;
            float gyl = ((q0 - a0) + 2.f*(q1 - a1) + (q2 - a2)) * 0.125f;
            float gyh = ((q1 - a1) + 2.f*(q2 - a2) + (q3 - a3)) * 0.125f;
            perc[c]      = pk2(m1, m2);
            perc[16 + c] = pk2(gxl, gxh);
            perc[32 + c] = pk2(gyl, gyh);
            if (c == 0) {
                float t0 = fmaxf(fmaxf(a0,a1),a2);
                float t1 = fmaxf(fmaxf(m0,m1),m2);
                float t2 = fmaxf(fmaxf(q0,q1),q2);
                premax_lo = fmaxf(fmaxf(t0,t1),t2);
                float u0 = fmaxf(fmaxf(a1,a2),a3);
                float u1 = fmaxf(fmaxf(m1,m2),m3);
                float u2 = fmaxf(fmaxf(q1,q2),q3);
                premax_hi = fmaxf(fmaxf(u0,u1),u2);
            }
        }

        // ---- cur = W2 * relu(W1 * perc) + cell ----
        float curl[16], curh[16];
        #pragma unroll
        for (int j = 0; j < 16; j++) { curl[j] = lo2(perc[j]); curh[j] = hi2(perc[j]); }

        for (int o = 0; o < 48; o += 2) {
            unsigned long long acc0 = 0ull, acc1 = 0ull;
            const unsigned long long* wr0 = sw1 + o*48;
            const unsigned long long* wr1 = wr0 + 48;
            #pragma unroll
            for (int k = 0; k < 48; k++) {
                fma2(acc0, perc[k], wr0[k]);
                fma2(acc1, perc[k], wr1[k]);
            }
            float h0l = fmaxf(lo2(acc0), 0.f), h0h = fmaxf(hi2(acc0), 0.f);
            float h1l = fmaxf(lo2(acc1), 0.f), h1h = fmaxf(hi2(acc1), 0.f);
            const float2* w2c = sw2p + (o >> 1)*16;
            #pragma unroll
            for (int j = 0; j < 16; j++) {
                float2 wj = w2c[j];
                curl[j] = fmaf(h0l, wj.x, fmaf(h1l, wj.y, curl[j]));
                curh[j] = fmaf(h0h, wj.x, fmaf(h1h, wj.y, curh[j]));
            }
        }

        // ---- store cur (vectorized) + pre mask ----
        const int gy = gy0 + r, gx = gx0 + 2*ix;
        size_t base = (((size_t)n*CCH)*Hh + gy)*Ww + gx;
        #pragma unroll
        for (int j = 0; j < 16; j++) {
            *reinterpret_cast<float2*>(g_cur + base + (size_t)j*Hh*Ww) = make_float2(curl[j], curh[j]);
        }
        int pb = (n*Hh + gy)*Ww + gx;
        uchar2 pm;
        pm.x = (premax_lo > 0.1f) ? 1 : 0;
        pm.y = (premax_hi > 0.1f) ? 1 : 0;
        *reinterpret_cast<uchar2*>(g_pre + pb) = pm;
    }
}

// Kernel 2: post mask (3x3 maxpool of cur ch0, -inf border) & apply pre&post
__global__ void mask_kernel(float* __restrict__ outfinal, int writeOut)
{
    int p = blockIdx.x*blockDim.x + threadIdx.x;   // over NB*Hh*Ww
    if (p >= NB*Hh*Ww) return;
    int x = p % Ww;
    int y = (p / Ww) % Hh;
    int n = p / (Hh*Ww);
    const float* c0 = g_cur + (size_t)n*CCH*Hh*Ww;
    float m = -1e30f;
    #pragma unroll
    for (int dy = -1; dy <= 1; dy++) {
        int yy = y + dy;
        if (yy < 0 || yy >= Hh) continue;
        const float* row = c0 + yy*Ww;
        #pragma unroll
        for (int dx = -1; dx <= 1; dx++) {
            int xx = x + dx;
            if (xx < 0 || xx >= Ww) continue;
            m = fmaxf(m, row[xx]);
        }
    }
    bool alive = (m > 0.1f) && (g_pre[p] != 0);
    size_t base = ((size_t)n*CCH)*Hh*Ww + (size_t)y*Ww + x;
    #pragma unroll
    for (int c = 0; c < CCH; c++) {
        float v = alive ? g_cur[base + (size_t)c*Hh*Ww] : 0.0f;
        g_cellA[base + (size_t)c*Hh*Ww] = v;
        if (writeOut && c >= 1 && c <= 10)
            outfinal[(((size_t)n*10 + (c-1))*Hh + y)*Ww + x] = v;
    }
}

extern "C" void kernel_launch(void* const* d_in, const int* in_sizes, int n_in,
                              void* d_out, int out_size)
{
    const float *inp = nullptr, *w1 = nullptr, *w2 = nullptr;
    for (int i = 0; i < n_in; i++) {
        if (in_sizes[i] == 48*48)      w1 = (const float*)d_in[i];
        else if (in_sizes[i] == 16*48) w2 = (const float*)d_in[i];
        else                           inp = (const float*)d_in[i];
    }
    float* out = (float*)d_out;

    const int smemBytes = (CCH*IH*IWP + 2*48*48 + 2*16*24) * 4;  // 61824
    cudaFuncSetAttribute(step_kernel, cudaFuncAttributeMaxDynamicSharedMemorySize, smemBytes);

    init_kernel<<<(NB*CCH*Hh*Ww + 255)/256, 256>>>(inp);

    dim3 g1(Ww/TW, Hh/TH, NB);   // (4, 8, 32)
    const int g2 = (NB*Hh*Ww + 255)/256;
    for (int it = 0; it < NITER; it++) {
        step_kernel<<<g1, 128, smemBytes>>>(w1, w2);
        mask_kernel<<<g2, 256>>>(out, (it == NITER-1) ? 1 : 0);
    }
}